// round 7
// baseline (speedup 1.0000x reference)
#include <cuda_runtime.h>
#include <cstdint>

// Static problem:
//   req_to_token:      [4096, 65536] int32  (single huge input, found by size)
//   req_pool_indices:  [1024] int32 in [0,4096)
//   page_kernel_lens:  [1024] int32 in [1,65536], lens[0]==65536 (pinned)
//   out (float32):     [1024, 1024]
// out[b,p] = float( req_to_token[pool[b], p*64] >> 6 )  if p < ceil(len[b]/64)
//            else 0.0f
//
// R7: replace scoreboarded LDG gathers (bound by the ~41-64 per-SM
// outstanding-load cap; R5/R6 were shape-insensitive at ~11us) with
// cp.async 4B copies into smem. LDGSTS has no observed depth cap and
// streams completions without the register-return/MSHR path. Masked
// pages use the src-size=0 zero-fill form (no divergence, no OOB read).

#define PAGE_SIZE 64
#define MAX_CTX   65536
#define MAX_PAGES 1024
#define BATCH     1024
#define POOL      4096
#define THREADS   256

__device__ __forceinline__ uint32_t smem_u32(const void* p) {
    return (uint32_t)__cvta_generic_to_shared(p);
}

__device__ __forceinline__ void cpasync_4(uint32_t dst, const void* src, int src_sz) {
    asm volatile("cp.async.ca.shared.global [%0], [%1], 4, %2;"
                 :: "r"(dst), "l"(src), "r"(src_sz) : "memory");
}

__global__ __launch_bounds__(THREADS)
void kv_page_index_kernel(const int* __restrict__ req_to_token,
                          const int* __restrict__ small0,
                          const int* __restrict__ small1,
                          float* __restrict__ out)
{
    __shared__ int s_tok[MAX_PAGES];   // 4 KB

    // Disambiguate by data invariant: lens[0] == 65536 > 4095 >= all pool ids.
    const bool s0_is_lens = (__ldg(&small0[0]) > 4095);
    const int* __restrict__ pools = s0_is_lens ? small1 : small0;
    const int* __restrict__ lens  = s0_is_lens ? small0 : small1;

    const int b    = blockIdx.x;                    // grid == BATCH (static)
    const int pool = __ldg(&pools[b]) & (POOL - 1); // clamp: fault-proof
    const int len  = __ldg(&lens[b]);
    int num_pages  = (len + PAGE_SIZE - 1) >> 6;
    if (num_pages < 0)         num_pages = 0;
    if (num_pages > MAX_PAGES) num_pages = MAX_PAGES;

    const int* __restrict__ row =
        req_to_token + (long long)pool * (long long)MAX_CTX;

    const int p0 = threadIdx.x << 2;                // 4 consecutive pages/thread
    const uint32_t s_dst = smem_u32(&s_tok[p0]);

    // 4 independent 4B async copies; masked pages zero-fill (src_sz=0).
    // Address stays in-bounds even when masked (p < MAX_PAGES always).
    cpasync_4(s_dst + 0,  row + (p0 + 0) * PAGE_SIZE, (p0 + 0 < num_pages) ? 4 : 0);
    cpasync_4(s_dst + 4,  row + (p0 + 1) * PAGE_SIZE, (p0 + 1 < num_pages) ? 4 : 0);
    cpasync_4(s_dst + 8,  row + (p0 + 2) * PAGE_SIZE, (p0 + 2 < num_pages) ? 4 : 0);
    cpasync_4(s_dst + 12, row + (p0 + 3) * PAGE_SIZE, (p0 + 3 < num_pages) ? 4 : 0);

    asm volatile("cp.async.wait_all;" ::: "memory");

    // Each thread reads back only its own smem words — no __syncthreads needed.
    const int4 t = *reinterpret_cast<const int4*>(&s_tok[p0]);

    float4 v;
    v.x = (float)(t.x >> 6);
    v.y = (float)(t.y >> 6);
    v.z = (float)(t.z >> 6);
    v.w = (float)(t.w >> 6);

    *reinterpret_cast<float4*>(out + (long long)b * MAX_PAGES + p0) = v;
}

extern "C" void kernel_launch(void* const* d_in, const int* in_sizes, int n_in,
                              void* d_out, int out_size)
{
    // req_to_token = the LARGEST input (robust to bytes-vs-elements units).
    int big_i = 0;
    for (int i = 1; i < n_in; i++)
        if (in_sizes[i] > in_sizes[big_i]) big_i = i;

    const int* big = (const int*)d_in[big_i];
    const int* small_arr[2] = {big, big};
    int ns = 0;
    for (int i = 0; i < n_in && ns < 2; i++)
        if (i != big_i) small_arr[ns++] = (const int*)d_in[i];

    kv_page_index_kernel<<<BATCH, THREADS>>>(big, small_arr[0], small_arr[1],
                                             (float*)d_out);
}

// round 8
// speedup vs baseline: 1.2610x; 1.2610x over previous
#include <cuda_runtime.h>
#include <cuda.h>
#include <cstdint>
#include <cstring>

// Static problem:
//   req_to_token:      [4096, 65536] int32  (single huge input, found by size)
//   req_pool_indices:  [1024] int32 in [0,4096)
//   page_kernel_lens:  [1024] int32 in [1,65536], lens[0]==65536 (pinned)
//   out (float32):     [1024, 1024]
// out[b,p] = float( req_to_token[pool[b], p*64] >> 6 ) if p < ceil(len[b]/64) else 0
//
// R8: gather via TMA. View the table as a 3D tensor [64, 1024, 4096] with
// strides (4B, 256B, 256KB); a box {4,64,1} at coords (0, 64*i, pool) bulk-
// loads 64 strided pages (16B each) into smem. Request generation moves off
// the SM (which R5-R7 proved is not improvable) into the TMA engines.

#define PAGE_SIZE 64
#define MAX_CTX   65536
#define MAX_PAGES 1024
#define BATCH     1024
#define POOL      4096
#define THREADS   128

#define BOX_PAGES   64
#define NBOX_MAX    (MAX_PAGES / BOX_PAGES)      // 16
#define BOX_BYTES   (BOX_PAGES * 16)             // 1024 B (16 B per page)

__device__ __forceinline__ uint32_t smem_u32(const void* p) {
    return (uint32_t)__cvta_generic_to_shared(p);
}

// ---------------- TMA kernel ----------------
__global__ __launch_bounds__(THREADS)
void kv_tma_kernel(const __grid_constant__ CUtensorMap tmap,
                   const int* __restrict__ small0,
                   const int* __restrict__ small1,
                   float* __restrict__ out)
{
    __shared__ alignas(128) int4 s_pg[MAX_PAGES];   // 16 KB: one int4 (16B) per page
    __shared__ alignas(8) uint64_t s_mbar;

    const bool s0_is_lens = (__ldg(&small0[0]) > 4095);
    const int* __restrict__ pools = s0_is_lens ? small1 : small0;
    const int* __restrict__ lens  = s0_is_lens ? small0 : small1;

    const int b    = blockIdx.x;
    const int pool = __ldg(&pools[b]) & (POOL - 1);
    const int len  = __ldg(&lens[b]);
    int num_pages  = (len + PAGE_SIZE - 1) >> 6;
    if (num_pages < 1)         num_pages = 1;
    if (num_pages > MAX_PAGES) num_pages = MAX_PAGES;
    const int nbox = (num_pages + BOX_PAGES - 1) >> 6;   // 1..16

    const uint32_t mbar = smem_u32(&s_mbar);

    if (threadIdx.x == 0) {
        asm volatile("mbarrier.init.shared.b64 [%0], 1;" :: "r"(mbar) : "memory");
    }
    __syncthreads();

    if (threadIdx.x == 0) {
        asm volatile("mbarrier.arrive.expect_tx.shared.b64 _, [%0], %1;"
                     :: "r"(mbar), "r"((uint32_t)(nbox * BOX_BYTES)) : "memory");
        const CUtensorMap* tm = &tmap;
        uint32_t dst = smem_u32(&s_pg[0]);
        #pragma unroll 1
        for (int i = 0; i < nbox; i++) {
            asm volatile(
                "cp.async.bulk.tensor.3d.shared::cta.global.tile.mbarrier::complete_tx::bytes "
                "[%0], [%1, {%2, %3, %4}], [%5];"
                :: "r"(dst + i * BOX_BYTES), "l"(tm),
                   "r"(0), "r"(i * BOX_PAGES), "r"(pool),
                   "r"(mbar) : "memory");
        }
    }
    __syncthreads();

    // Wait for TMA completion (parity 0; fresh barrier each launch).
    {
        uint32_t done;
        asm volatile(
            "{\n\t.reg .pred p;\n\t"
            "mbarrier.try_wait.parity.acquire.cta.shared::cta.b64 p, [%1], 0;\n\t"
            "selp.b32 %0, 1, 0, p;\n\t}"
            : "=r"(done) : "r"(mbar) : "memory");
        if (!done) {
            asm volatile(
                "{\n\t.reg .pred P1;\n\t"
                "WL_%=:\n\t"
                "mbarrier.try_wait.parity.acquire.cta.shared::cta.b64 P1, [%0], 0, 0x989680;\n\t"
                "@P1 bra.uni WD_%=;\n\t"
                "bra.uni WL_%=;\n\t"
                "WD_%=:\n\t}"
                :: "r"(mbar) : "memory");
        }
    }

    // Convert + masked store. Thread t handles pages {j*128 + t}:
    // conflict-free LDS.128 (lanes 16B apart), coalesced 4B stores.
    float* __restrict__ orow = out + (long long)b * MAX_PAGES;
    #pragma unroll
    for (int j = 0; j < MAX_PAGES / THREADS; j++) {
        const int p = j * THREADS + threadIdx.x;
        const int4 q = s_pg[p];
        orow[p] = (p < num_pages) ? (float)(q.x >> 6) : 0.0f;
    }
}

// ---------------- fallback: proven 10.9us LDG kernel ----------------
__global__ __launch_bounds__(256)
void kv_ldg_kernel(const int* __restrict__ req_to_token,
                   const int* __restrict__ small0,
                   const int* __restrict__ small1,
                   float* __restrict__ out)
{
    const bool s0_is_lens = (__ldg(&small0[0]) > 4095);
    const int* __restrict__ pools = s0_is_lens ? small1 : small0;
    const int* __restrict__ lens  = s0_is_lens ? small0 : small1;

    const int b    = blockIdx.x;
    const int pool = __ldg(&pools[b]) & (POOL - 1);
    const int len  = __ldg(&lens[b]);
    int num_pages  = (len + PAGE_SIZE - 1) >> 6;
    if (num_pages < 0)         num_pages = 0;
    if (num_pages > MAX_PAGES) num_pages = MAX_PAGES;

    const int* __restrict__ row =
        req_to_token + (long long)pool * (long long)MAX_CTX;
    const int p0 = threadIdx.x << 2;

    float4 v;
    v.x = (p0 + 0 < num_pages) ? (float)(__ldg(&row[(p0 + 0) * PAGE_SIZE]) >> 6) : 0.0f;
    v.y = (p0 + 1 < num_pages) ? (float)(__ldg(&row[(p0 + 1) * PAGE_SIZE]) >> 6) : 0.0f;
    v.z = (p0 + 2 < num_pages) ? (float)(__ldg(&row[(p0 + 2) * PAGE_SIZE]) >> 6) : 0.0f;
    v.w = (p0 + 3 < num_pages) ? (float)(__ldg(&row[(p0 + 3) * PAGE_SIZE]) >> 6) : 0.0f;

    *reinterpret_cast<float4*>(out + (long long)b * MAX_PAGES + p0) = v;
}

// ---------------- host ----------------
typedef CUresult (*EncodeTiledFn)(
    CUtensorMap*, CUtensorMapDataType, cuuint32_t, void*,
    const cuuint64_t*, const cuuint64_t*, const cuuint32_t*, const cuuint32_t*,
    CUtensorMapInterleave, CUtensorMapSwizzle, CUtensorMapL2promotion,
    CUtensorMapFloatOOBfill);

extern "C" void kernel_launch(void* const* d_in, const int* in_sizes, int n_in,
                              void* d_out, int out_size)
{
    // req_to_token = the LARGEST input (robust to size-unit ambiguity).
    int big_i = 0;
    for (int i = 1; i < n_in; i++)
        if (in_sizes[i] > in_sizes[big_i]) big_i = i;

    const int* big = (const int*)d_in[big_i];
    const int* small_arr[2] = {big, big};
    int ns = 0;
    for (int i = 0; i < n_in && ns < 2; i++)
        if (i != big_i) small_arr[ns++] = (const int*)d_in[i];

    // Build (and cache) the tensormap for this table pointer.
    static CUtensorMap s_tmap;
    static const void* s_tmap_for = nullptr;
    static bool s_tma_ok = false;

    if (s_tmap_for != (const void*)big) {
        s_tmap_for = (const void*)big;
        s_tma_ok = false;

        EncodeTiledFn encode = nullptr;
        cudaDriverEntryPointQueryResult qr;
        if (cudaGetDriverEntryPointByVersion("cuTensorMapEncodeTiled",
                                             (void**)&encode, 12000,
                                             cudaEnableDefault, &qr) == cudaSuccess
            && encode != nullptr) {
            // View: [x=64 tokens, y=1024 pages, z=4096 rows], int32.
            cuuint64_t dims[3]    = {64, MAX_PAGES, POOL};
            cuuint64_t strides[2] = {PAGE_SIZE * 4ull,            // 256 B page stride
                                     (cuuint64_t)MAX_CTX * 4ull}; // 256 KB row stride
            cuuint32_t box[3]     = {4, BOX_PAGES, 1};            // 16 B per page
            cuuint32_t estr[3]    = {1, 1, 1};
            CUresult r = encode(&s_tmap, CU_TENSOR_MAP_DATA_TYPE_INT32, 3,
                                (void*)big, dims, strides, box, estr,
                                CU_TENSOR_MAP_INTERLEAVE_NONE,
                                CU_TENSOR_MAP_SWIZZLE_NONE,
                                CU_TENSOR_MAP_L2_PROMOTION_NONE,
                                CU_TENSOR_MAP_FLOAT_OOB_FILL_NONE);
            s_tma_ok = (r == CUDA_SUCCESS);
        }
    }

    if (s_tma_ok) {
        kv_tma_kernel<<<BATCH, THREADS>>>(s_tmap, small_arr[0], small_arr[1],
                                          (float*)d_out);
    } else {
        kv_ldg_kernel<<<BATCH, 256>>>(big, small_arr[0], small_arr[1],
                                      (float*)d_out);
    }
}